// round 2
// baseline (speedup 1.0000x reference)
#include <cuda_runtime.h>
#include <math.h>

#define Bn 32
#define Nn 128
#define Cc 128
#define HEe 64

// ---------------- scratch (device globals; no allocs allowed) ----------------
__device__ float g_u[Bn*Nn*HEe];
__device__ float g_v[Bn*Nn*HEe];
__device__ float g_s[Bn*Nn*Nn];
__device__ float g_P[Bn*Nn*Nn];
__device__ float g_rs[Bn*Nn];
__device__ float g_An[Bn*Nn*Nn];
__device__ float g_DA[Bn*Nn];
__device__ float g_DE[Bn*Nn];
__device__ float g_LA[Bn*Nn*Nn];
__device__ float g_LE[Bn*Nn*Nn];
__device__ float g_X[Bn*Nn*512];
__device__ float g_Xcat[Bn*Nn*1536];
__device__ float g_pool[Bn*512];

// ---------------- generic batched GEMM: C = alpha*A@B + beta*Dsrc ------------
// 64x64 block tile, BK=16, 256 threads, 4x4 per thread, fp32.
__global__ void gemm_k(const float* __restrict__ Ag, int lda, long sA,
                       const float* __restrict__ Bg, int ldb, long sB,
                       const float* __restrict__ Dg, int ldd, long sD,
                       float* __restrict__ Cg, int ldc, long sC,
                       int M, int N, int K, float alpha, float beta)
{
    const float* Ab = Ag + (long)blockIdx.z * sA;
    const float* Bb = Bg + (long)blockIdx.z * sB;
    float*       Cb = Cg + (long)blockIdx.z * sC;
    const float* Db = Dg ? (Dg + (long)blockIdx.z * sD) : nullptr;

    __shared__ float As[16][64];
    __shared__ float Bs[16][64];

    int tid = threadIdx.x;
    int tx = tid & 15, ty = tid >> 4;
    int m0 = blockIdx.y * 64, n0 = blockIdx.x * 64;

    float acc[4][4];
#pragma unroll
    for (int i = 0; i < 4; i++)
#pragma unroll
        for (int j = 0; j < 4; j++) acc[i][j] = 0.f;

    for (int k0 = 0; k0 < K; k0 += 16) {
#pragma unroll
        for (int t = 0; t < 4; t++) {
            int idx = tid + t * 256;          // 1024 elems
            int m = idx >> 4, kk = idx & 15;
            int gm = m0 + m, gk = k0 + kk;
            As[kk][m] = (gm < M && gk < K) ? Ab[(long)gm * lda + gk] : 0.f;
        }
#pragma unroll
        for (int t = 0; t < 4; t++) {
            int idx = tid + t * 256;
            int kk = idx >> 6, n = idx & 63;
            int gk = k0 + kk, gn = n0 + n;
            Bs[kk][n] = (gk < K && gn < N) ? Bb[(long)gk * ldb + gn] : 0.f;
        }
        __syncthreads();
#pragma unroll
        for (int kk = 0; kk < 16; kk++) {
            float4 a4 = *reinterpret_cast<const float4*>(&As[kk][ty * 4]);
            float4 b4 = *reinterpret_cast<const float4*>(&Bs[kk][tx * 4]);
            float a[4] = {a4.x, a4.y, a4.z, a4.w};
            float b[4] = {b4.x, b4.y, b4.z, b4.w};
#pragma unroll
            for (int i = 0; i < 4; i++)
#pragma unroll
                for (int j = 0; j < 4; j++) acc[i][j] += a[i] * b[j];
        }
        __syncthreads();
    }

#pragma unroll
    for (int i = 0; i < 4; i++) {
        int gm = m0 + ty * 4 + i;
        if (gm >= M) continue;
#pragma unroll
        for (int j = 0; j < 4; j++) {
            int gn = n0 + tx * 4 + j;
            if (gn >= N) continue;
            float v = alpha * acc[i][j];
            if (Db) v += beta * Db[(long)gm * ldd + gn];
            Cb[(long)gm * ldc + gn] = v;
        }
    }
}

static inline void gemm(const float* A, int lda, long sA,
                        const float* B, int ldb, long sB,
                        const float* D, int ldd, long sD,
                        float* C, int ldc, long sC,
                        int M, int N, int K, float alpha, float beta, int batch)
{
    dim3 grid((N + 63) / 64, (M + 63) / 64, batch);
    gemm_k<<<grid, 256>>>(A, lda, sA, B, ldb, sB, D, ldd, sD, C, ldc, sC,
                          M, N, K, alpha, beta);
}

// ---------------- edge MLP pairwise scores -----------------------------------
// s[b,i,j] = sum_h relu(u[b,i,h]+v[b,j,h]+eb1[h]) * eW2[h] + eb2
__global__ void edge_score_k(const float* __restrict__ u, const float* __restrict__ v,
                             const float* __restrict__ eb1, const float* __restrict__ eW2,
                             const float* __restrict__ eb2, float* __restrict__ s)
{
    __shared__ float su[16][65];
    __shared__ float sv[16][65];
    __shared__ float sb[64];
    __shared__ float sw[64];
    int b = blockIdx.z;
    int i0 = blockIdx.y * 16, j0 = blockIdx.x * 16;
    int tid = threadIdx.x;      // 256
    if (tid < 64) { sb[tid] = eb1[tid]; sw[tid] = eW2[tid]; }
#pragma unroll
    for (int t = 0; t < 4; t++) {
        int idx = tid + t * 256;        // 1024
        int r = idx >> 6, c = idx & 63;
        su[r][c] = u[((long)(b * Nn + i0 + r)) * HEe + c];
        sv[r][c] = v[((long)(b * Nn + j0 + r)) * HEe + c];
    }
    __syncthreads();
    int ii = tid >> 4, jj = tid & 15;
    float acc = eb2[0];
#pragma unroll
    for (int h = 0; h < 64; h++) {
        float t = su[ii][h] + sv[jj][h] + sb[h];
        acc += fmaxf(t, 0.f) * sw[h];
    }
    s[((long)(b * Nn + i0 + ii)) * Nn + (j0 + jj)] = acc;
}

// P[b,i,j] = (i<j) ? exp(0.5*(s_ij + s_ji)) * mask_i * mask_j : 0
__global__ void p_k(const float* __restrict__ s, const float* __restrict__ mask,
                    float* __restrict__ P)
{
    int idx = blockIdx.x * blockDim.x + threadIdx.x;
    if (idx >= Bn * Nn * Nn) return;
    int j = idx & (Nn - 1);
    int i = (idx >> 7) & (Nn - 1);
    int b = idx >> 14;
    float val = 0.f;
    if (i < j) {
        float mm = mask[b * Nn + i] * mask[b * Nn + j];
        if (mm != 0.f)
            val = expf(0.5f * (s[idx] + s[((long)(b * Nn + j)) * Nn + i])) * mm;
    }
    P[idx] = val;
}

__global__ void row_sum_k(const float* __restrict__ P, float* __restrict__ rs)
{
    int row = blockIdx.x;   // b*Nn + i
    __shared__ float sm[128];
    float acc = P[(long)row * Nn + threadIdx.x];
    sm[threadIdx.x] = acc;
    __syncthreads();
    for (int sft = 64; sft > 0; sft >>= 1) {
        if (threadIdx.x < sft) sm[threadIdx.x] += sm[threadIdx.x + sft];
        __syncthreads();
    }
    if (threadIdx.x == 0) {
        float r = sm[0];
        rs[row] = (r == 0.f) ? 1.f : r;
    }
}

// An_sym[b,i,j] = P[b,i,j]/rs[b,i] + P[b,j,i]/rs[b,j]
__global__ void an_k(const float* __restrict__ P, const float* __restrict__ rs,
                     float* __restrict__ An)
{
    int idx = blockIdx.x * blockDim.x + threadIdx.x;
    if (idx >= Bn * Nn * Nn) return;
    int j = idx & (Nn - 1);
    int i = (idx >> 7) & (Nn - 1);
    int b = idx >> 14;
    An[idx] = P[idx] / rs[b * Nn + i] +
              P[((long)(b * Nn + j)) * Nn + i] / rs[b * Nn + j];
}

// D[b,j] = (sum_i Ar[b,i,j] + 1e-5)^(-1/2)   (column sums)
__global__ void col_D_k(const float* __restrict__ Ar, float* __restrict__ D)
{
    int b = blockIdx.x;
    int j = threadIdx.x;    // 128
    float acc = 0.f;
    for (int i = 0; i < Nn; i++) acc += Ar[((long)(b * Nn + i)) * Nn + j];
    D[b * Nn + j] = 1.f / sqrtf(acc + 1e-5f);
}

// L[b,i,j] = D[b,i]*Ar[b,i,j]*D[b,j]
__global__ void build_L_k(const float* __restrict__ Ar, const float* __restrict__ D,
                          float* __restrict__ L)
{
    int idx = blockIdx.x * blockDim.x + threadIdx.x;
    if (idx >= Bn * Nn * Nn) return;
    int j = idx & (Nn - 1);
    int i = (idx >> 7) & (Nn - 1);
    int b = idx >> 14;
    L[idx] = D[b * Nn + i] * Ar[idx] * D[b * Nn + j];
}

// copy T0 into Xcat cols [0,fin) and [3fin,4fin)
__global__ void copy_T0_k(const float* __restrict__ X, float* __restrict__ Xcat, int fin)
{
    int idx = blockIdx.x * blockDim.x + threadIdx.x;
    int total = Bn * Nn * fin;
    if (idx >= total) return;
    int c = idx % fin;
    int row = idx / fin;
    float v = X[idx];
    long base = (long)row * (6 * fin);
    Xcat[base + c] = v;
    Xcat[base + 3 * fin + c] = v;
}

// in-place: X = relu( ((X + bias)*mask - m) * rsq * g + be )
__global__ void bn_ep_k(float* __restrict__ X, const float* __restrict__ mask,
                        const float* __restrict__ bias, const float* __restrict__ gg,
                        const float* __restrict__ be, const float* __restrict__ mm,
                        const float* __restrict__ vv, int f)
{
    int idx = blockIdx.x * blockDim.x + threadIdx.x;
    int total = Bn * Nn * f;
    if (idx >= total) return;
    int c = idx % f;
    int row = idx / f;
    float val = X[idx] + bias[c];
    val *= mask[row];
    val = (val - mm[c]) / sqrtf(vv[c] + 1e-5f) * gg[c] + be[c];
    X[idx] = fmaxf(val, 0.f);
}

__global__ void pool_k(const float* __restrict__ X, float* __restrict__ pool)
{
    int b = blockIdx.x;
    int c = threadIdx.x;    // 512
    float m = X[((long)(b * Nn)) * 512 + c];
    for (int n = 1; n < Nn; n++)
        m = fmaxf(m, X[((long)(b * Nn + n)) * 512 + c]);
    pool[b * 512 + c] = m;
}

// out = (pool @ fW1 + fb1) @ fW2 + fb2   (one block per batch element)
__global__ void classifier_k(const float* __restrict__ pool,
                             const float* __restrict__ fW1, const float* __restrict__ fb1,
                             const float* __restrict__ fW2, const float* __restrict__ fb2,
                             float* __restrict__ out)
{
    int b = blockIdx.x;
    int t = threadIdx.x;    // 256
    __shared__ float hid[256];
    float acc = fb1[t];
    const float* pb = pool + b * 512;
    for (int k = 0; k < 512; k++) acc += pb[k] * fW1[k * 256 + t];
    hid[t] = acc;
    __syncthreads();
    if (t < 10) {
        float o = fb2[t];
        for (int k = 0; k < 256; k++) o += hid[k] * fW2[k * 10 + t];
        out[b * 10 + t] = o;
    }
}

// ---------------- host orchestration -----------------------------------------
extern "C" void kernel_launch(void* const* d_in, const int* in_sizes, int n_in,
                              void* d_out, int out_size)
{
    const float* x    = (const float*)d_in[0];
    const float* A    = (const float*)d_in[1];
    const float* mask = (const float*)d_in[2];
    const float* eW1  = (const float*)d_in[3];
    const float* eb1  = (const float*)d_in[4];
    const float* eW2  = (const float*)d_in[5];
    const float* eb2  = (const float*)d_in[6];
    const float* gW[3]  = {(const float*)d_in[7],  (const float*)d_in[13], (const float*)d_in[19]};
    const float* gb[3]  = {(const float*)d_in[8],  (const float*)d_in[14], (const float*)d_in[20]};
    const float* gg[3]  = {(const float*)d_in[9],  (const float*)d_in[15], (const float*)d_in[21]};
    const float* gbe[3] = {(const float*)d_in[10], (const float*)d_in[16], (const float*)d_in[22]};
    const float* gm[3]  = {(const float*)d_in[11], (const float*)d_in[17], (const float*)d_in[23]};
    const float* gv[3]  = {(const float*)d_in[12], (const float*)d_in[18], (const float*)d_in[24]};
    const float* fW1 = (const float*)d_in[25];
    const float* fb1 = (const float*)d_in[26];
    const float* fW2 = (const float*)d_in[27];
    const float* fb2 = (const float*)d_in[28];
    float* out = (float*)d_out;

    float *u, *v, *s, *P, *rs, *An, *DA, *DE, *LA, *LE, *X, *Xcat, *pool;
    cudaGetSymbolAddress((void**)&u,    g_u);
    cudaGetSymbolAddress((void**)&v,    g_v);
    cudaGetSymbolAddress((void**)&s,    g_s);
    cudaGetSymbolAddress((void**)&P,    g_P);
    cudaGetSymbolAddress((void**)&rs,   g_rs);
    cudaGetSymbolAddress((void**)&An,   g_An);
    cudaGetSymbolAddress((void**)&DA,   g_DA);
    cudaGetSymbolAddress((void**)&DE,   g_DE);
    cudaGetSymbolAddress((void**)&LA,   g_LA);
    cudaGetSymbolAddress((void**)&LE,   g_LE);
    cudaGetSymbolAddress((void**)&X,    g_X);
    cudaGetSymbolAddress((void**)&Xcat, g_Xcat);
    cudaGetSymbolAddress((void**)&pool, g_pool);

    const int BN = Bn * Nn;          // 4096
    const int BNN = Bn * Nn * Nn;    // 524288

    // 1) u = x @ eW1[:128], v = x @ eW1[128:]
    gemm(x, Cc, 0, eW1,            HEe, 0, nullptr, 0, 0, u, HEe, 0, BN, HEe, Cc, 1.f, 0.f, 1);
    gemm(x, Cc, 0, eW1 + Cc * HEe, HEe, 0, nullptr, 0, 0, v, HEe, 0, BN, HEe, Cc, 1.f, 0.f, 1);

    // 2) pairwise edge scores
    {
        dim3 gs(Nn / 16, Nn / 16, Bn);
        edge_score_k<<<gs, 256>>>(u, v, eb1, eW2, eb2, s);
    }

    // 3) masked upper-tri exp, row sums, symmetrized normalized adjacency
    p_k<<<(BNN + 255) / 256, 256>>>(s, mask, P);
    row_sum_k<<<BN, 128>>>(P, rs);
    an_k<<<(BNN + 255) / 256, 256>>>(P, rs, An);

    // 4) degree-normalized Laplacians for both relations (layer-invariant)
    col_D_k<<<Bn, Nn>>>(A, DA);
    col_D_k<<<Bn, Nn>>>(An, DE);
    build_L_k<<<(BNN + 255) / 256, 256>>>(A, DA, LA);
    build_L_k<<<(BNN + 255) / 256, 256>>>(An, DE, LE);

    // 5) three graph-conv layers
    const int FILT[3] = {64, 256, 512};
    const float* Xin = x;
    int fin = Cc;
    for (int li = 0; li < 3; li++) {
        int f = FILT[li];
        int ldx = 6 * fin;
        long sX = (long)Nn * fin;
        long sXc = (long)Nn * ldx;
        long sL = (long)Nn * Nn;

        copy_T0_k<<<(BN * fin + 255) / 256, 256>>>(Xin, Xcat, fin);
        // T1 = L @ X
        gemm(LA, Nn, sL, Xin, fin, sX, nullptr, 0, 0, Xcat + fin,     ldx, sXc, Nn, fin, Nn, 1.f, 0.f, Bn);
        gemm(LE, Nn, sL, Xin, fin, sX, nullptr, 0, 0, Xcat + 4 * fin, ldx, sXc, Nn, fin, Nn, 1.f, 0.f, Bn);
        // T2 = 2 L @ T1 - X
        gemm(LA, Nn, sL, Xcat + fin,     ldx, sXc, Xin, fin, sX, Xcat + 2 * fin, ldx, sXc, Nn, fin, Nn, 2.f, -1.f, Bn);
        gemm(LE, Nn, sL, Xcat + 4 * fin, ldx, sXc, Xin, fin, sX, Xcat + 5 * fin, ldx, sXc, Nn, fin, Nn, 2.f, -1.f, Bn);
        // dense: H = Xcat @ W
        gemm(Xcat, ldx, 0, gW[li], f, 0, nullptr, 0, 0, X, f, 0, BN, f, 6 * fin, 1.f, 0.f, 1);
        // bias + mask + BN(eval) + relu, in place
        bn_ep_k<<<(BN * f + 255) / 256, 256>>>(X, mask, gb[li], gg[li], gbe[li], gm[li], gv[li], f);

        Xin = X;
        fin = f;
    }

    // 6) max pool over nodes + classifier
    pool_k<<<Bn, 512>>>(X, pool);
    classifier_k<<<Bn, 256>>>(pool, fW1, fb1, fW2, fb2, out);
}

// round 5
// speedup vs baseline: 1.5141x; 1.5141x over previous
#include <cuda_runtime.h>
#include <math.h>

#define Bn 32
#define Nn 128
#define Cc 128
#define HEe 64

// ---------------- scratch (device globals; no allocs allowed) ----------------
__device__ float g_uv[2*Bn*Nn*HEe];
__device__ float g_s[Bn*Nn*Nn];
__device__ float g_P[Bn*Nn*Nn];
__device__ float g_rs[Bn*Nn];
__device__ float g_An[Bn*Nn*Nn];
__device__ float g_DA[Bn*Nn];
__device__ float g_DE[Bn*Nn];
__device__ float g_L[2*Bn*Nn*Nn];      // [rel][b][N][N]: LA then LE
__device__ float g_X[Bn*Nn*512];
__device__ float g_Xcat[Bn*Nn*1536];
__device__ float g_pool[Bn*512];

// ---------------- templated batched GEMM ------------------------------------
// C = alpha*A@B (+ beta*D)  [MODE 0]   or   relu(BN(mask*(A@B + bias)))  [MODE 1]
// No bounds checks: M%BM==0, N%BN==0, K%16==0 guaranteed by caller.
// Batch addressing: z over gridDim.z; zb=z%bmod, zr=z/bmod.
//   A += z*sA ; B += zb*sB + zr*sB2 ; C += zb*sC + zr*sC2 ; D += zb*sD
template<int BM, int BN, int TM, int TN, int MODE>
__global__ void __launch_bounds__(256) gemm_t(
    const float* __restrict__ Ag, int lda, long sA,
    const float* __restrict__ Bg, int ldb, long sB, long sB2,
    const float* __restrict__ Dg, int ldd, long sD,
    float* __restrict__ Cg, int ldc, long sC, long sC2,
    int K, float alpha, float beta, int bmod,
    const float* __restrict__ bias, const float* __restrict__ gg,
    const float* __restrict__ be,  const float* __restrict__ mm,
    const float* __restrict__ vv,  const float* __restrict__ mask)
{
    constexpr int TX = BN / TN;            // threads along N
    constexpr int A4 = (BM * 16) / (256 * 4);
    constexpr int B4 = (BN * 16) / (256 * 4);

    __shared__ float As[2][16][BM];
    __shared__ float Bs[2][16][BN];

    const int tid = threadIdx.x;
    const int tx = tid % TX, ty = tid / TX;
    const int m0 = blockIdx.y * BM, n0 = blockIdx.x * BN;
    const int z = blockIdx.z;
    const int zb = z % bmod, zr = z / bmod;

    const float* Ab = Ag + (long)z * sA;
    const float* Bb = Bg + (long)zb * sB + (long)zr * sB2;
    float*       Cb = Cg + (long)zb * sC + (long)zr * sC2;
    const float* Db = Dg ? (Dg + (long)zb * sD) : nullptr;

    float acc[TM][TN];
#pragma unroll
    for (int i = 0; i < TM; i++)
#pragma unroll
        for (int j = 0; j < TN; j++) acc[i][j] = 0.f;

    float4 pa[A4], pb[B4];

    // ---- load tile 0 directly into buffer 0 ----
#pragma unroll
    for (int q = 0; q < A4; q++) {
        int g4 = tid + q * 256;
        int row = g4 >> 2, kq = (g4 & 3) * 4;
        float4 r = *reinterpret_cast<const float4*>(&Ab[(long)(m0 + row) * lda + kq]);
        As[0][kq + 0][row] = r.x; As[0][kq + 1][row] = r.y;
        As[0][kq + 2][row] = r.z; As[0][kq + 3][row] = r.w;
    }
#pragma unroll
    for (int q = 0; q < B4; q++) {
        int g4 = tid + q * 256;
        int row = g4 / (BN / 4), c4 = g4 % (BN / 4);
        *reinterpret_cast<float4*>(&Bs[0][row][c4 * 4]) =
            *reinterpret_cast<const float4*>(&Bb[(long)row * ldb + n0 + c4 * 4]);
    }
    __syncthreads();

    const int nk = K / 16;
    for (int kt = 0; kt < nk; kt++) {
        int cur = kt & 1;
        if (kt + 1 < nk) {
            int k0 = (kt + 1) * 16;
#pragma unroll
            for (int q = 0; q < A4; q++) {
                int g4 = tid + q * 256;
                int row = g4 >> 2, kq = (g4 & 3) * 4;
                pa[q] = *reinterpret_cast<const float4*>(&Ab[(long)(m0 + row) * lda + k0 + kq]);
            }
#pragma unroll
            for (int q = 0; q < B4; q++) {
                int g4 = tid + q * 256;
                int row = g4 / (BN / 4), c4 = g4 % (BN / 4);
                pb[q] = *reinterpret_cast<const float4*>(&Bb[(long)(k0 + row) * ldb + n0 + c4 * 4]);
            }
        }
#pragma unroll
        for (int kk = 0; kk < 16; kk++) {
            float a[TM], b[TN];
#pragma unroll
            for (int i = 0; i < TM / 4; i++)
                *reinterpret_cast<float4*>(&a[i * 4]) =
                    *reinterpret_cast<const float4*>(&As[cur][kk][ty * TM + i * 4]);
#pragma unroll
            for (int j = 0; j < TN / 4; j++)
                *reinterpret_cast<float4*>(&b[j * 4]) =
                    *reinterpret_cast<const float4*>(&Bs[cur][kk][tx * TN + j * 4]);
#pragma unroll
            for (int i = 0; i < TM; i++)
#pragma unroll
                for (int j = 0; j < TN; j++) acc[i][j] += a[i] * b[j];
        }
        if (kt + 1 < nk) {
            int nxt = cur ^ 1;
#pragma unroll
            for (int q = 0; q < A4; q++) {
                int g4 = tid + q * 256;
                int row = g4 >> 2, kq = (g4 & 3) * 4;
                As[nxt][kq + 0][row] = pa[q].x; As[nxt][kq + 1][row] = pa[q].y;
                As[nxt][kq + 2][row] = pa[q].z; As[nxt][kq + 3][row] = pa[q].w;
            }
#pragma unroll
            for (int q = 0; q < B4; q++) {
                int g4 = tid + q * 256;
                int row = g4 / (BN / 4), c4 = g4 % (BN / 4);
                *reinterpret_cast<float4*>(&Bs[nxt][row][c4 * 4]) = pb[q];
            }
            __syncthreads();
        }
    }

#pragma unroll
    for (int i = 0; i < TM; i++) {
        int gm = m0 + ty * TM + i;
#pragma unroll
        for (int j = 0; j < TN; j++) {
            int gn = n0 + tx * TN + j;
            float v = alpha * acc[i][j];
            if (MODE == 0) {
                if (Db) v += beta * Db[(long)gm * ldd + gn];
            } else {
                v = (v + bias[gn]) * mask[gm];
                v = (v - mm[gn]) * rsqrtf(vv[gn] + 1e-5f) * gg[gn] + be[gn];
                v = fmaxf(v, 0.f);
            }
            Cb[(long)gm * ldc + gn] = v;
        }
    }
}

// ---------------- edge MLP pairwise scores -----------------------------------
__global__ void edge_score_k(const float* __restrict__ u, const float* __restrict__ v,
                             const float* __restrict__ eb1, const float* __restrict__ eW2,
                             const float* __restrict__ eb2, float* __restrict__ s)
{
    __shared__ float su[16][65];
    __shared__ float sv[16][65];
    __shared__ float sb[64];
    __shared__ float sw[64];
    int b = blockIdx.z;
    int i0 = blockIdx.y * 16, j0 = blockIdx.x * 16;
    int tid = threadIdx.x;      // 256
    if (tid < 64) { sb[tid] = eb1[tid]; sw[tid] = eW2[tid]; }
#pragma unroll
    for (int t = 0; t < 4; t++) {
        int idx = tid + t * 256;
        int r = idx >> 6, c = idx & 63;
        su[r][c] = u[((long)(b * Nn + i0 + r)) * HEe + c];
        sv[r][c] = v[((long)(b * Nn + j0 + r)) * HEe + c];
    }
    __syncthreads();
    int ii = tid >> 4, jj = tid & 15;
    float acc = eb2[0];
#pragma unroll
    for (int h = 0; h < 64; h++) {
        float t = su[ii][h] + sv[jj][h] + sb[h];
        acc += fmaxf(t, 0.f) * sw[h];
    }
    s[((long)(b * Nn + i0 + ii)) * Nn + (j0 + jj)] = acc;
}

// P row + row-sum fused: one block per (b,i)
__global__ void p_rs_k(const float* __restrict__ s, const float* __restrict__ mask,
                       float* __restrict__ P, float* __restrict__ rs)
{
    int row = blockIdx.x;             // b*Nn + i
    int b = row >> 7, i = row & 127;
    int j = threadIdx.x;              // 128
    float val = 0.f;
    if (i < j) {
        float mmv = mask[b * Nn + i] * mask[b * Nn + j];
        if (mmv != 0.f)
            val = expf(0.5f * (s[(long)row * Nn + j] + s[((long)(b * Nn + j)) * Nn + i])) * mmv;
    }
    P[(long)row * Nn + j] = val;
    __shared__ float sm[128];
    sm[j] = val;
    __syncthreads();
    for (int sft = 64; sft > 0; sft >>= 1) {
        if (j < sft) sm[j] += sm[j + sft];
        __syncthreads();
    }
    if (j == 0) {
        float r = sm[0];
        rs[row] = (r == 0.f) ? 1.f : r;
    }
}

__global__ void an_k(const float* __restrict__ P, const float* __restrict__ rs,
                     float* __restrict__ An)
{
    int idx = blockIdx.x * blockDim.x + threadIdx.x;
    if (idx >= Bn * Nn * Nn) return;
    int j = idx & (Nn - 1);
    int i = (idx >> 7) & (Nn - 1);
    int b = idx >> 14;
    An[idx] = P[idx] / rs[b * Nn + i] +
              P[((long)(b * Nn + j)) * Nn + i] / rs[b * Nn + j];
}

// D[b,j] = (sum_i Ar[b,i,j] + 1e-5)^(-1/2)   (column sums)
__global__ void col_D_k(const float* __restrict__ Ar, float* __restrict__ D)
{
    int b = blockIdx.x;
    int j = threadIdx.x;    // 128
    float acc = 0.f;
    for (int i = 0; i < Nn; i++) acc += Ar[((long)(b * Nn + i)) * Nn + j];
    D[b * Nn + j] = 1.f / sqrtf(acc + 1e-5f);
}

__global__ void build_L_k(const float* __restrict__ Ar, const float* __restrict__ D,
                          float* __restrict__ L)
{
    int idx = blockIdx.x * blockDim.x + threadIdx.x;
    if (idx >= Bn * Nn * Nn) return;
    int j = idx & (Nn - 1);
    int i = (idx >> 7) & (Nn - 1);
    int b = idx >> 14;
    L[idx] = D[b * Nn + i] * Ar[idx] * D[b * Nn + j];
}

__global__ void copy_T0_k(const float* __restrict__ X, float* __restrict__ Xcat, int fin)
{
    int idx = blockIdx.x * blockDim.x + threadIdx.x;
    int total = Bn * Nn * fin;
    if (idx >= total) return;
    int c = idx % fin;
    int row = idx / fin;
    float v = X[idx];
    long base = (long)row * (6 * fin);
    Xcat[base + c] = v;
    Xcat[base + 3 * fin + c] = v;
}

__global__ void pool_k(const float* __restrict__ X, float* __restrict__ pool)
{
    int b = blockIdx.x;
    int c = threadIdx.x;    // 512
    float m = X[((long)(b * Nn)) * 512 + c];
    for (int n = 1; n < Nn; n++)
        m = fmaxf(m, X[((long)(b * Nn + n)) * 512 + c]);
    pool[b * 512 + c] = m;
}

__global__ void classifier_k(const float* __restrict__ pool,
                             const float* __restrict__ fW1, const float* __restrict__ fb1,
                             const float* __restrict__ fW2, const float* __restrict__ fb2,
                             float* __restrict__ out)
{
    int b = blockIdx.x;
    int t = threadIdx.x;    // 256
    __shared__ float hid[256];
    float acc = fb1[t];
    const float* pb = pool + b * 512;
    for (int k = 0; k < 512; k++) acc += pb[k] * fW1[k * 256 + t];
    hid[t] = acc;
    __syncthreads();
    if (t < 10) {
        float o = fb2[t];
        for (int k = 0; k < 256; k++) o += hid[k] * fW2[k * 10 + t];
        out[b * 10 + t] = o;
    }
}

// ---------------- host orchestration -----------------------------------------
extern "C" void kernel_launch(void* const* d_in, const int* in_sizes, int n_in,
                              void* d_out, int out_size)
{
    const float* x    = (const float*)d_in[0];
    const float* A    = (const float*)d_in[1];
    const float* mask = (const float*)d_in[2];
    const float* eW1  = (const float*)d_in[3];
    const float* eb1  = (const float*)d_in[4];
    const float* eW2  = (const float*)d_in[5];
    const float* eb2  = (const float*)d_in[6];
    const float* gW[3]  = {(const float*)d_in[7],  (const float*)d_in[13], (const float*)d_in[19]};
    const float* gb[3]  = {(const float*)d_in[8],  (const float*)d_in[14], (const float*)d_in[20]};
    const float* gg[3]  = {(const float*)d_in[9],  (const float*)d_in[15], (const float*)d_in[21]};
    const float* gbe[3] = {(const float*)d_in[10], (const float*)d_in[16], (const float*)d_in[22]};
    const float* gm[3]  = {(const float*)d_in[11], (const float*)d_in[17], (const float*)d_in[23]};
    const float* gv[3]  = {(const float*)d_in[12], (const float*)d_in[18], (const float*)d_in[24]};
    const float* fW1 = (const float*)d_in[25];
    const float* fb1 = (const float*)d_in[26];
    const float* fW2 = (const float*)d_in[27];
    const float* fb2 = (const float*)d_in[28];
    float* out = (float*)d_out;

    float *uv, *s, *P, *rs, *An, *DA, *DE, *L, *X, *Xcat, *pool;
    cudaGetSymbolAddress((void**)&uv,   g_uv);
    cudaGetSymbolAddress((void**)&s,    g_s);
    cudaGetSymbolAddress((void**)&P,    g_P);
    cudaGetSymbolAddress((void**)&rs,   g_rs);
    cudaGetSymbolAddress((void**)&An,   g_An);
    cudaGetSymbolAddress((void**)&DA,   g_DA);
    cudaGetSymbolAddress((void**)&DE,   g_DE);
    cudaGetSymbolAddress((void**)&L,    g_L);
    cudaGetSymbolAddress((void**)&X,    g_X);
    cudaGetSymbolAddress((void**)&Xcat, g_Xcat);
    cudaGetSymbolAddress((void**)&pool, g_pool);

    const int BN = Bn * Nn;          // 4096
    const int BNN = Bn * Nn * Nn;    // 524288
    const long sL = (long)Nn * Nn;

    // 1) u|v = x @ eW1 halves, one batched launch (z=2)
    {
        dim3 grid(1, BN / 64, 2);
        gemm_t<64,64,4,4,0><<<grid, 256>>>(
            x, Cc, 0,
            eW1, HEe, (long)Cc * HEe, 0,
            nullptr, 0, 0,
            uv, HEe, (long)BN * HEe, 0,
            Cc, 1.f, 0.f, 2,
            nullptr, nullptr, nullptr, nullptr, nullptr, nullptr);
    }

    // 2) pairwise edge scores
    {
        dim3 gs(Nn / 16, Nn / 16, Bn);
        edge_score_k<<<gs, 256>>>(uv, uv + (long)BN * HEe, eb1, eW2, eb2, s);
    }

    // 3) masked upper-tri exp + row sums (fused), then symmetrized normalization
    p_rs_k<<<BN, 128>>>(s, mask, P, rs);
    an_k<<<(BNN + 255) / 256, 256>>>(P, rs, An);

    // 4) degree-normalized Laplacians (layer-invariant), LA|LE contiguous
    col_D_k<<<Bn, Nn>>>(A, DA);
    col_D_k<<<Bn, Nn>>>(An, DE);
    build_L_k<<<(BNN + 255) / 256, 256>>>(A, DA, L);
    build_L_k<<<(BNN + 255) / 256, 256>>>(An, DE, L + BNN);

    // 5) three graph-conv layers
    const int FILT[3] = {64, 256, 512};
    const float* Xin = x;
    int fin = Cc;
    for (int li = 0; li < 3; li++) {
        int f = FILT[li];
        int ldx = 6 * fin;
        long sX = (long)Nn * fin;
        long sXc = (long)Nn * ldx;

        copy_T0_k<<<(BN * fin + 255) / 256, 256>>>(Xin, Xcat, fin);

        // T1 = L @ X for both relations in one launch (z = 64)
        {
            dim3 grid(fin / 64, Nn / 64, 64);
            gemm_t<64,64,4,4,0><<<grid, 256>>>(
                L, Nn, sL,
                Xin, fin, sX, 0,
                nullptr, 0, 0,
                Xcat + fin, ldx, sXc, 3L * fin,
                Nn, 1.f, 0.f, 32,
                nullptr, nullptr, nullptr, nullptr, nullptr, nullptr);
        }
        // T2 = 2*L @ T1 - T0 for both relations
        {
            dim3 grid(fin / 64, Nn / 64, 64);
            gemm_t<64,64,4,4,0><<<grid, 256>>>(
                L, Nn, sL,
                Xcat + fin, ldx, sXc, 3L * fin,
                Xin, fin, sX,
                Xcat + 2 * fin, ldx, sXc, 3L * fin,
                Nn, 2.f, -1.f, 32,
                nullptr, nullptr, nullptr, nullptr, nullptr, nullptr);
        }
        // dense: X = relu(BN(mask * (Xcat @ W + b)))  (fused epilogue)
        if (f >= 128) {
            dim3 grid(f / 128, BN / 128, 1);
            gemm_t<128,128,8,8,1><<<grid, 256>>>(
                Xcat, ldx, 0,
                gW[li], f, 0, 0,
                nullptr, 0, 0,
                X, f, 0, 0,
                6 * fin, 1.f, 0.f, 1,
                gb[li], gg[li], gbe[li], gm[li], gv[li], mask);
        } else {
            dim3 grid(f / 64, BN / 64, 1);
            gemm_t<64,64,4,4,1><<<grid, 256>>>(
                Xcat, ldx, 0,
                gW[li], f, 0, 0,
                nullptr, 0, 0,
                X, f, 0, 0,
                6 * fin, 1.f, 0.f, 1,
                gb[li], gg[li], gbe[li], gm[li], gv[li], mask);
        }

        Xin = X;
        fin = f;
    }

    // 6) max pool over nodes + classifier
    pool_k<<<Bn, 512>>>(X, pool);
    classifier_k<<<Bn, 256>>>(pool, fW1, fb1, fW2, fb2, out);
}